// round 1
// baseline (speedup 1.0000x reference)
#include <cuda_runtime.h>
#include <cuda_bf16.h>
#include <cstdint>

// Problem constants
#define NB   32      // batch
#define C    1024    // channels
#define S    1024    // spatial (32*32)
#define BM   128
#define BN   128
#define BK   64
#define TPB  256
#define TILES_PER_BATCH 36          // 8*9/2 upper-triangle block tiles
#define NBLK2 (NB * TILES_PER_BATCH) // 1152
#define SPAD 72                      // padded smem row stride (bf16 elems): 144B -> conflict-free ldmatrix

// Scratch: normalized rows in bf16 (64 MB), per-block partial sums
__device__ __nv_bfloat16 g_xn[(size_t)NB * C * S];
__device__ float g_partials[NBLK2];

// ---------------------------------------------------------------------------
// Kernel 1: per-row mean-center + L2-normalize, fp32 -> bf16
// One block per (n,c) row of 1024 elements. 256 threads x float4.
// ---------------------------------------------------------------------------
__global__ __launch_bounds__(TPB) void normalize_kernel(const float* __restrict__ x) {
    const int row = blockIdx.x;            // 0 .. NB*C-1
    const size_t base = (size_t)row * S;
    const int tid = threadIdx.x;

    float4 v = reinterpret_cast<const float4*>(x + base)[tid];
    float s  = v.x + v.y + v.z + v.w;
    float ss = v.x*v.x + v.y*v.y + v.z*v.z + v.w*v.w;

    #pragma unroll
    for (int o = 16; o; o >>= 1) {
        s  += __shfl_xor_sync(0xFFFFFFFFu, s,  o);
        ss += __shfl_xor_sync(0xFFFFFFFFu, ss, o);
    }

    __shared__ float red[16];
    __shared__ float bc[2];
    const int wid = tid >> 5;
    if ((tid & 31) == 0) { red[wid] = s; red[8 + wid] = ss; }
    __syncthreads();
    if (tid == 0) {
        float S0 = 0.f, SS0 = 0.f;
        #pragma unroll
        for (int w = 0; w < 8; w++) { S0 += red[w]; SS0 += red[8 + w]; }
        float mean = S0 * (1.0f / S);
        float rss  = fmaxf(SS0 - S0 * mean, 0.0f);   // sum((x-mean)^2)
        float nrm  = sqrtf(rss);
        bc[0] = mean;
        bc[1] = 1.0f / (nrm + 1e-8f);
    }
    __syncthreads();
    const float mean  = bc[0];
    const float scale = bc[1];

    __nv_bfloat162 h0 = __floats2bfloat162_rn((v.x - mean) * scale, (v.y - mean) * scale);
    __nv_bfloat162 h1 = __floats2bfloat162_rn((v.z - mean) * scale, (v.w - mean) * scale);
    uint2 packed;
    packed.x = *reinterpret_cast<uint32_t*>(&h0);
    packed.y = *reinterpret_cast<uint32_t*>(&h1);
    reinterpret_cast<uint2*>(&g_xn[base])[tid] = packed;
}

// ---------------------------------------------------------------------------
// mma.sync helpers (bf16, fp32 accum)
// ---------------------------------------------------------------------------
__device__ __forceinline__ void ldm_x4(uint32_t& r0, uint32_t& r1, uint32_t& r2, uint32_t& r3,
                                       uint32_t addr) {
    asm volatile("ldmatrix.sync.aligned.m8n8.x4.shared.b16 {%0,%1,%2,%3}, [%4];\n"
                 : "=r"(r0), "=r"(r1), "=r"(r2), "=r"(r3) : "r"(addr));
}

__device__ __forceinline__ void mma16816(float* d, const uint32_t* a, const uint32_t* b) {
    asm volatile("mma.sync.aligned.m16n8k16.row.col.f32.bf16.bf16.f32 "
                 "{%0,%1,%2,%3}, {%4,%5,%6,%7}, {%8,%9}, {%0,%1,%2,%3};\n"
                 : "+f"(d[0]), "+f"(d[1]), "+f"(d[2]), "+f"(d[3])
                 : "r"(a[0]), "r"(a[1]), "r"(a[2]), "r"(a[3]), "r"(b[0]), "r"(b[1]));
}

// ---------------------------------------------------------------------------
// Kernel 2: fused Gram-tile GEMM + masked |.| reduction.
// Upper-triangle 128x128 tiles only (symmetry -> 2x less tensor work).
// 8 warps, each computes a 64x32 sub-tile via m16n8k16 bf16 mma.
// ---------------------------------------------------------------------------
__global__ __launch_bounds__(TPB) void gram_abs_kernel() {
    __shared__ __align__(16) __nv_bfloat16 sA[BM][SPAD];
    __shared__ __align__(16) __nv_bfloat16 sB[BN][SPAD];

    const int bx = blockIdx.x;
    const int batch = bx / TILES_PER_BATCH;
    int t = bx % TILES_PER_BATCH;
    int ti = 0;
    while (t >= 8 - ti) { t -= 8 - ti; ti++; }
    const int tj = ti + t;                 // ti <= tj

    const int tid  = threadIdx.x;
    const int wid  = tid >> 5;
    const int lane = tid & 31;
    const int warp_m = wid & 1;            // 2 x 64 rows
    const int warp_n = wid >> 1;           // 4 x 32 cols

    const __nv_bfloat16* gA = g_xn + ((size_t)batch * C + ti * BM) * S;
    const __nv_bfloat16* gB = g_xn + ((size_t)batch * C + tj * BN) * S;

    // ldmatrix lane addressing (byte addresses into shared)
    const uint32_t sA_base = (uint32_t)__cvta_generic_to_shared(&sA[0][0]);
    const uint32_t sB_base = (uint32_t)__cvta_generic_to_shared(&sB[0][0]);
    // A: lanes 0-15 -> rows 0-15 @ col k; lanes 16-31 -> rows 0-15 @ col k+8
    const int a_row = warp_m * 64 + (lane & 15);
    const int a_col = (lane >> 4) * 8;
    // B (x4 = two n-frags): lanes0-7 rows n0+l @k; 8-15 rows n0+l @k+8; 16-23 rows n0+8+l @k; 24-31 @k+8
    const int b_row = warp_n * 32 + (lane & 7) + ((lane >> 4) << 3);
    const int b_col = ((lane >> 3) & 1) * 8;

    float acc[4][4][4];
    #pragma unroll
    for (int i = 0; i < 4; i++)
        #pragma unroll
        for (int j = 0; j < 4; j++)
            #pragma unroll
            for (int r = 0; r < 4; r++) acc[i][j][r] = 0.0f;

    for (int k0 = 0; k0 < S; k0 += BK) {
        // cooperative tile load: 128 rows x 64 bf16 (128B/row), uint4 per thread x4 iters
        #pragma unroll
        for (int it = 0; it < 4; it++) {
            int idx = it * TPB + tid;
            int r = idx >> 3;
            int c = (idx & 7) * 8;
            *reinterpret_cast<uint4*>(&sA[r][c]) =
                *reinterpret_cast<const uint4*>(gA + (size_t)r * S + k0 + c);
            *reinterpret_cast<uint4*>(&sB[r][c]) =
                *reinterpret_cast<const uint4*>(gB + (size_t)r * S + k0 + c);
        }
        __syncthreads();

        #pragma unroll
        for (int kk = 0; kk < BK; kk += 16) {
            uint32_t a[4][4];
            #pragma unroll
            for (int mf = 0; mf < 4; mf++) {
                uint32_t addr = sA_base + (uint32_t)(((a_row + mf * 16) * SPAD + a_col + kk) * 2);
                ldm_x4(a[mf][0], a[mf][1], a[mf][2], a[mf][3], addr);
            }
            uint32_t b[4][2];
            {
                uint32_t addr0 = sB_base + (uint32_t)((b_row * SPAD + b_col + kk) * 2);
                ldm_x4(b[0][0], b[0][1], b[1][0], b[1][1], addr0);
                uint32_t addr1 = sB_base + (uint32_t)(((b_row + 16) * SPAD + b_col + kk) * 2);
                ldm_x4(b[2][0], b[2][1], b[3][0], b[3][1], addr1);
            }
            #pragma unroll
            for (int mf = 0; mf < 4; mf++)
                #pragma unroll
                for (int nf = 0; nf < 4; nf++)
                    mma16816(acc[mf][nf], a[mf], b[nf]);
        }
        __syncthreads();
    }

    // Epilogue: sum |corr| over strictly-upper (gj > gi) entries
    const int groupID = lane >> 2;
    const int tid4    = lane & 3;
    float lsum = 0.0f;
    #pragma unroll
    for (int mf = 0; mf < 4; mf++) {
        #pragma unroll
        for (int nf = 0; nf < 4; nf++) {
            int gi = ti * BM + warp_m * 64 + mf * 16 + groupID;
            int gj = tj * BN + warp_n * 32 + nf * 8 + tid4 * 2;
            if (gj     > gi)     lsum += fabsf(acc[mf][nf][0]);
            if (gj + 1 > gi)     lsum += fabsf(acc[mf][nf][1]);
            if (gj     > gi + 8) lsum += fabsf(acc[mf][nf][2]);
            if (gj + 1 > gi + 8) lsum += fabsf(acc[mf][nf][3]);
        }
    }
    #pragma unroll
    for (int o = 16; o; o >>= 1) lsum += __shfl_xor_sync(0xFFFFFFFFu, lsum, o);

    __shared__ float red[8];
    if (lane == 0) red[wid] = lsum;
    __syncthreads();
    if (tid == 0) {
        float bsum = 0.f;
        #pragma unroll
        for (int w = 0; w < 8; w++) bsum += red[w];
        g_partials[bx] = bsum;
    }
}

// ---------------------------------------------------------------------------
// Kernel 3: deterministic final reduction + scaling.
// total_offdiag = 2*U;  avg = total/comb/2/N = U/(comb*N), comb = C*(C-1)/2
// ---------------------------------------------------------------------------
__global__ __launch_bounds__(TPB) void finalize_kernel(float* __restrict__ out) {
    float s = 0.0f;
    for (int i = threadIdx.x; i < NBLK2; i += TPB) s += g_partials[i];
    #pragma unroll
    for (int o = 16; o; o >>= 1) s += __shfl_xor_sync(0xFFFFFFFFu, s, o);

    __shared__ float red[8];
    const int wid = threadIdx.x >> 5;
    if ((threadIdx.x & 31) == 0) red[wid] = s;
    __syncthreads();
    if (threadIdx.x == 0) {
        float tot = 0.f;
        #pragma unroll
        for (int w = 0; w < 8; w++) tot += red[w];
        const float comb = (float)C * (C - 1) * 0.5f;   // 523776
        out[0] = tot / (comb * (float)NB);
    }
}

// ---------------------------------------------------------------------------
extern "C" void kernel_launch(void* const* d_in, const int* in_sizes, int n_in,
                              void* d_out, int out_size) {
    const float* x = (const float*)d_in[0];
    float* out = (float*)d_out;

    normalize_kernel<<<NB * C, TPB>>>(x);
    gram_abs_kernel<<<NBLK2, TPB>>>();
    finalize_kernel<<<1, TPB>>>(out);
}

// round 3
// speedup vs baseline: 1.4121x; 1.4121x over previous
#include <cuda_runtime.h>
#include <cuda_bf16.h>
#include <cstdint>

// ---------------------------------------------------------------------------
// Problem constants
// ---------------------------------------------------------------------------
#define NB   32
#define C    1024
#define S    1024
#define BM   128
#define BN   128
#define BK   64                       // 64 bf16 = 128 B per tile row
#define NCHUNK (S / BK)               // 16
#define TILES_PER_BATCH 36            // upper-triangle 8x8 block grid
#define NBLK2 (NB * TILES_PER_BATCH)  // 1152
#define TPB  256
#define STAGES 3
#define TILE_BYTES (BM * 128)         // 16384 per A (or B) buffer
#define STAGE_BYTES (2 * TILE_BYTES)  // A + B
#define DSMEM_BYTES (STAGES * STAGE_BYTES)   // 98304

// Scratch
__device__ __nv_bfloat16 g_xn[(size_t)NB * C * S];
__device__ float g_partials[NBLK2];

// ---------------------------------------------------------------------------
// PTX helpers
// ---------------------------------------------------------------------------
__device__ __forceinline__ void cp_async16(uint32_t smem_addr, const void* gptr) {
    asm volatile("cp.async.cg.shared.global [%0], [%1], 16;" :: "r"(smem_addr), "l"(gptr));
}
#define CP_COMMIT() asm volatile("cp.async.commit_group;" ::: "memory")
#define CP_WAIT(n)  asm volatile("cp.async.wait_group %0;" :: "n"(n) : "memory")

__device__ __forceinline__ void ldm_x4(uint32_t& r0, uint32_t& r1, uint32_t& r2, uint32_t& r3,
                                       uint32_t addr) {
    asm volatile("ldmatrix.sync.aligned.m8n8.x4.shared.b16 {%0,%1,%2,%3}, [%4];\n"
                 : "=r"(r0), "=r"(r1), "=r"(r2), "=r"(r3) : "r"(addr));
}

__device__ __forceinline__ void mma16816(float* d, const uint32_t* a, const uint32_t* b) {
    asm volatile("mma.sync.aligned.m16n8k16.row.col.f32.bf16.bf16.f32 "
                 "{%0,%1,%2,%3}, {%4,%5,%6,%7}, {%8,%9}, {%0,%1,%2,%3};\n"
                 : "+f"(d[0]), "+f"(d[1]), "+f"(d[2]), "+f"(d[3])
                 : "r"(a[0]), "r"(a[1]), "r"(a[2]), "r"(a[3]), "r"(b[0]), "r"(b[1]));
}

// XOR swizzle for 128B rows: 16B chunk c in row r stored at chunk (c ^ (r&7))
__device__ __forceinline__ uint32_t swz(int row, int col_elems) {
    // col_elems multiple of 8 (one 16B chunk)
    uint32_t chunk = (uint32_t)(col_elems >> 3);
    return (uint32_t)(row * 128) + (((chunk ^ ((uint32_t)row & 7u)) << 4));
}

// ---------------------------------------------------------------------------
// Kernel 1: normalize — one WARP per row (no block syncs, MLP=8)
// ---------------------------------------------------------------------------
__global__ __launch_bounds__(256) void normalize_kernel(const float* __restrict__ x) {
    const int wid  = threadIdx.x >> 5;
    const int lane = threadIdx.x & 31;
    const int row  = blockIdx.x * 8 + wid;
    const size_t base = (size_t)row * S;
    const float4* in4 = reinterpret_cast<const float4*>(x + base);

    float4 v[8];
    float s = 0.f, ss = 0.f;
    #pragma unroll
    for (int i = 0; i < 8; i++) {
        v[i] = in4[lane + 32 * i];
        s  += v[i].x + v[i].y + v[i].z + v[i].w;
        ss += v[i].x * v[i].x + v[i].y * v[i].y + v[i].z * v[i].z + v[i].w * v[i].w;
    }
    #pragma unroll
    for (int o = 16; o; o >>= 1) {
        s  += __shfl_xor_sync(0xFFFFFFFFu, s,  o);
        ss += __shfl_xor_sync(0xFFFFFFFFu, ss, o);
    }
    const float mean  = s * (1.0f / S);
    const float rss   = fmaxf(ss - s * mean, 0.0f);
    const float scale = 1.0f / (sqrtf(rss) + 1e-8f);

    uint2* out4 = reinterpret_cast<uint2*>(g_xn + base);
    #pragma unroll
    for (int i = 0; i < 8; i++) {
        __nv_bfloat162 h0 = __floats2bfloat162_rn((v[i].x - mean) * scale, (v[i].y - mean) * scale);
        __nv_bfloat162 h1 = __floats2bfloat162_rn((v[i].z - mean) * scale, (v[i].w - mean) * scale);
        uint2 p;
        p.x = *reinterpret_cast<uint32_t*>(&h0);
        p.y = *reinterpret_cast<uint32_t*>(&h1);
        out4[lane + 32 * i] = p;
    }
}

// ---------------------------------------------------------------------------
// Kernel 2: Gram tile via mma.sync bf16, 3-stage cp.async pipeline,
// fused masked |.| reduction. 8 warps, each a 64x32 sub-tile.
// ---------------------------------------------------------------------------
__global__ __launch_bounds__(TPB, 2) void gram_abs_kernel() {
    extern __shared__ __align__(128) char dsmem[];
    __shared__ float s_red[8];

    const int tid  = threadIdx.x;
    const int wid  = tid >> 5;
    const int lane = tid & 31;
    const int warp_m = wid & 1;            // 2 x 64 rows
    const int warp_n = wid >> 1;           // 4 x 32 cols

    // tile decode (upper triangle)
    const int bx = blockIdx.x;
    const int batch = bx / TILES_PER_BATCH;
    int t = bx % TILES_PER_BATCH;
    int ti = 0;
    while (t >= 8 - ti) { t -= 8 - ti; ti++; }
    const int tj = ti + t;

    const __nv_bfloat16* gA = g_xn + ((size_t)batch * C + ti * BM) * S;
    const __nv_bfloat16* gB = g_xn + ((size_t)batch * C + tj * BN) * S;

    const uint32_t smem_base = (uint32_t)__cvta_generic_to_shared(dsmem);

    // loader for one K-chunk into stage buffer
    auto load_chunk = [&](int cch, int stage) {
        const int k0 = cch * BK;
        const uint32_t sA = smem_base + stage * STAGE_BYTES;
        const uint32_t sB = sA + TILE_BYTES;
        #pragma unroll
        for (int it = 0; it < 4; it++) {
            int idx = it * TPB + tid;         // 0..1023
            int r   = idx >> 3;
            int c16 = idx & 7;                // 16B chunk
            uint32_t dst = swz(r, c16 * 8);
            const size_t goff = (size_t)r * S + k0 + c16 * 8;
            cp_async16(sA + dst, gA + goff);
            cp_async16(sB + dst, gB + goff);
        }
    };

    // ldmatrix lane geometry
    const int a_row = warp_m * 64 + (lane & 15);
    const int a_col = (lane >> 4) * 8;
    const int b_row = warp_n * 32 + (lane & 7) + ((lane >> 4) << 3);
    const int b_col = ((lane >> 3) & 1) * 8;

    float acc[4][4][4];
    #pragma unroll
    for (int i = 0; i < 4; i++)
        #pragma unroll
        for (int j = 0; j < 4; j++)
            #pragma unroll
            for (int r = 0; r < 4; r++) acc[i][j][r] = 0.0f;

    // prologue: stages 0 and 1 in flight
    load_chunk(0, 0); CP_COMMIT();
    load_chunk(1, 1); CP_COMMIT();

    for (int cch = 0; cch < NCHUNK; cch++) {
        const int stage = cch % STAGES;
        CP_WAIT(1);            // chunk cch resident
        __syncthreads();       // visible to all warps; prior compute (cch-1) done by all

        // issue next load into the buffer freed by compute of chunk cch-1
        if (cch + 2 < NCHUNK) {
            load_chunk(cch + 2, (cch + 2) % STAGES);
            CP_COMMIT();
        }

        const uint32_t sA = smem_base + stage * STAGE_BYTES;
        const uint32_t sB = sA + TILE_BYTES;

        #pragma unroll
        for (int kk = 0; kk < BK; kk += 16) {
            uint32_t a[4][4];
            #pragma unroll
            for (int mf = 0; mf < 4; mf++) {
                uint32_t addr = sA + swz(a_row + mf * 16, a_col + kk);
                ldm_x4(a[mf][0], a[mf][1], a[mf][2], a[mf][3], addr);
            }
            uint32_t b[4][2];
            {
                uint32_t addr0 = sB + swz(b_row, b_col + kk);
                ldm_x4(b[0][0], b[0][1], b[1][0], b[1][1], addr0);
                uint32_t addr1 = sB + swz(b_row + 16, b_col + kk);
                ldm_x4(b[2][0], b[2][1], b[3][0], b[3][1], addr1);
            }
            #pragma unroll
            for (int mf = 0; mf < 4; mf++)
                #pragma unroll
                for (int nf = 0; nf < 4; nf++)
                    mma16816(acc[mf][nf], a[mf], b[nf]);
        }
        __syncthreads();   // all warps done reading stage before it is refilled
    }

    // Epilogue: sum |corr| over strictly-upper (gj > gi) entries
    const int groupID = lane >> 2;
    const int tid4    = lane & 3;
    float lsum = 0.0f;
    #pragma unroll
    for (int mf = 0; mf < 4; mf++) {
        #pragma unroll
        for (int nf = 0; nf < 4; nf++) {
            int gi = ti * BM + warp_m * 64 + mf * 16 + groupID;
            int gj = tj * BN + warp_n * 32 + nf * 8 + tid4 * 2;
            if (gj     > gi)     lsum += fabsf(acc[mf][nf][0]);
            if (gj + 1 > gi)     lsum += fabsf(acc[mf][nf][1]);
            if (gj     > gi + 8) lsum += fabsf(acc[mf][nf][2]);
            if (gj + 1 > gi + 8) lsum += fabsf(acc[mf][nf][3]);
        }
    }
    #pragma unroll
    for (int o = 16; o; o >>= 1) lsum += __shfl_xor_sync(0xFFFFFFFFu, lsum, o);

    if (lane == 0) s_red[wid] = lsum;
    __syncthreads();
    if (tid == 0) {
        float bsum = 0.f;
        #pragma unroll
        for (int w = 0; w < 8; w++) bsum += s_red[w];
        g_partials[bx] = bsum;
    }
}

// ---------------------------------------------------------------------------
// Kernel 3: deterministic final reduction + scaling.
// avg = U / (comb * N), comb = C*(C-1)/2 (total offdiag = 2U)
// ---------------------------------------------------------------------------
__global__ __launch_bounds__(256) void finalize_kernel(float* __restrict__ out) {
    float s = 0.0f;
    for (int i = threadIdx.x; i < NBLK2; i += 256) s += g_partials[i];
    #pragma unroll
    for (int o = 16; o; o >>= 1) s += __shfl_xor_sync(0xFFFFFFFFu, s, o);

    __shared__ float red[8];
    const int wid = threadIdx.x >> 5;
    if ((threadIdx.x & 31) == 0) red[wid] = s;
    __syncthreads();
    if (threadIdx.x == 0) {
        float tot = 0.f;
        #pragma unroll
        for (int w = 0; w < 8; w++) tot += red[w];
        const float comb = (float)C * (C - 1) * 0.5f;
        out[0] = tot / (comb * (float)NB);
    }
}

// ---------------------------------------------------------------------------
extern "C" void kernel_launch(void* const* d_in, const int* in_sizes, int n_in,
                              void* d_out, int out_size) {
    const float* x = (const float*)d_in[0];
    float* out = (float*)d_out;

    cudaFuncSetAttribute(gram_abs_kernel,
                         cudaFuncAttributeMaxDynamicSharedMemorySize, DSMEM_BYTES);

    normalize_kernel<<<NB * C / 8, 256>>>(x);
    gram_abs_kernel<<<NBLK2, TPB, DSMEM_BYTES>>>();
    finalize_kernel<<<1, 256>>>(out);
}